// round 7
// baseline (speedup 1.0000x reference)
#include <cuda_runtime.h>

// Problem constants (fixed instance: B=2048, T=2048, H=51)
#define H_  51
#define HP  52          // padded hidden
#define JP  208         // 4*HP gate count
#define RR  16          // batch rows per CTA
#define NT  640         // threads per CTA (20 warps)
#define TT  2048
#define BB  2048
#define PS  20          // smem partial stride

// Repacked weights (device globals; prep kernel fills them each launch)
__device__ float g_W1p[HP*JP];   // [k][j] layer-1 W_hh
__device__ float g_W2a[HP*JP];   // [k][j] layer-2 W_ih
__device__ float g_W2b[HP*JP];   // [k][j] layer-2 W_hh
__device__ float g_b1[JP];
__device__ float g_wx[JP];
__device__ float g_b2[JP];
__device__ float g_wlin[HP];
__device__ float g_blin[1];

__global__ void prep_kernel(const float* __restrict__ W_ih1, const float* __restrict__ W_hh1,
                            const float* __restrict__ b_ih1, const float* __restrict__ b_hh1,
                            const float* __restrict__ W_ih2, const float* __restrict__ W_hh2,
                            const float* __restrict__ b_ih2, const float* __restrict__ b_hh2,
                            const float* __restrict__ W_lin, const float* __restrict__ b_lin)
{
    int stride = gridDim.x * blockDim.x;
    int i0 = blockIdx.x * blockDim.x + threadIdx.x;
    for (int idx = i0; idx < HP*JP; idx += stride) {
        int k = idx / JP, j = idx % JP;
        int g = j / HP, n = j % HP;
        bool v = (n < H_) && (k < H_);
        int ro = g*H_ + n;
        g_W1p[idx] = v ? W_hh1[ro*H_ + k] : 0.f;
        g_W2a[idx] = v ? W_ih2[ro*H_ + k] : 0.f;
        g_W2b[idx] = v ? W_hh2[ro*H_ + k] : 0.f;
    }
    for (int j = i0; j < JP; j += stride) {
        int g = j / HP, n = j % HP;
        bool v = (n < H_);
        int ro = g*H_ + n;
        g_b1[j] = v ? (b_ih1[ro] + b_hh1[ro]) : 0.f;
        g_wx[j] = v ? W_ih1[ro] : 0.f;
        g_b2[j] = v ? (b_ih2[ro] + b_hh2[ro]) : 0.f;
    }
    for (int n = i0; n < HP; n += stride) g_wlin[n] = (n < H_) ? W_lin[n] : 0.f;
    if (i0 == 0) g_blin[0] = b_lin[0];
}

// HW tanh (single MUFU op)
__device__ __forceinline__ float tanha(float x) {
    float r; asm("tanh.approx.f32 %0, %1;" : "=f"(r) : "f"(x)); return r;
}
__device__ __forceinline__ float siga(float x) {
    return fmaf(0.5f, tanha(0.5f*x), 0.5f);
}

// ---- packed f32x2 helpers (PTX-only; ptxas won't auto-fuse) ----
__device__ __forceinline__ unsigned long long pk2(float w) {
    unsigned long long r;
    asm("mov.b64 %0, {%1, %1};" : "=l"(r) : "f"(w));
    return r;
}
__device__ __forceinline__ void fma2(unsigned long long& a, unsigned long long w, unsigned long long h) {
    asm("fma.rn.f32x2 %0, %1, %2, %3;" : "=l"(a) : "l"(w), "l"(h), "l"(a));
}

__global__ __launch_bounds__(NT, 1)
void lstm_kernel(const float* __restrict__ input, float* __restrict__ out)
{
    extern __shared__ float sm[];
    float* p1  = sm;                   // 416*PS
    float* p2  = p1 + 416*PS;          // 832*PS
    float* h1s = p2 + 832*PS;          // HP*RR  layout [k][r]
    float* h2s = h1s + HP*RR;
    float* xs  = h2s + HP*RR;          // RR
    float* wls = xs + RR;              // HP
    float* b2s = wls + HP;             // JP

    const int tid  = threadIdx.x;
    const int row0 = blockIdx.x * RR;

    const bool isP2  = (tid < 416);
    const bool isP1  = (tid >= 416) && (tid < 624);
    const bool isOut = (tid >= 624);
    const int orow   = tid - 624;

    // P2 worker: q = (kh*2 + src), j-pair (jp, jp+104), K=26
    const int q   = tid / 104;
    const int jp  = tid - q*104;
    const int src = q & 1;                  // 0 = W_ih2·h1, 1 = W_hh2·h2
    const int kh  = q >> 1;
    // P1 worker: k-half kh1, j-pair (jp1, jp1+104), K=26
    const int u   = tid - 416;
    const int kh1 = (u >= 0) ? (u / 104) : 0;
    const int jp1 = (u >= 0) ? (u - kh1*104) : 0;

    // update tasks: task tid for all threads; extra task 640+(tid-448) for tid>=448
    const int un  = tid >> 4, ur  = tid & 15;        // n 0..39
    const bool has2 = (tid >= 448);
    const int tk2 = 640 + (tid - 448);
    const int un2 = tk2 >> 4, ur2 = tk2 & 15;        // n 40..51

    // register-resident weights
    float wreg[52];
    float ba = 0.f, bb = 0.f, wxa = 0.f, wxb = 0.f;
    if (isP2) {
        const float* Ws = src ? g_W2b : g_W2a;
#pragma unroll
        for (int kk = 0; kk < 26; kk++) {
            wreg[kk]      = Ws[(kh*26 + kk)*JP + jp];
            wreg[26 + kk] = Ws[(kh*26 + kk)*JP + jp + 104];
        }
    } else if (isP1) {
#pragma unroll
        for (int kk = 0; kk < 26; kk++) {
            wreg[kk]      = g_W1p[(kh1*26 + kk)*JP + jp1];
            wreg[26 + kk] = g_W1p[(kh1*26 + kk)*JP + jp1 + 104];
        }
        ba = g_b1[jp1];  bb = g_b1[jp1 + 104];
        wxa = g_wx[jp1]; wxb = g_wx[jp1 + 104];
    } else {
#pragma unroll
        for (int kk = 0; kk < 52; kk++) wreg[kk] = 0.f;
    }
    const float blin = g_blin[0];

    // persistent cell state
    float c1 = 0.f, c2 = 0.f, c1x = 0.f, c2x = 0.f;

    for (int i = tid; i < HP*RR; i += NT) { h1s[i] = 0.f; h2s[i] = 0.f; }
    for (int i = tid; i < HP; i += NT) wls[i] = g_wlin[i];
    for (int i = tid; i < JP; i += NT) b2s[i] = g_b2[i];
    float x1hold = 0.f;
    if (tid >= RR && tid < 2*RR) {
        xs[tid - RR] = input[(row0 + tid - RR)*TT + 0];
        x1hold = input[(row0 + tid - RR)*TT + 1];
    }
    __syncthreads();

    // ================= prologue: phase1(0) + update1(0) =================
    if (isP1) {
        unsigned long long acc[16];
        if (kh1 == 0) {
            unsigned long long bpA = pk2(ba), wpA = pk2(wxa);
            unsigned long long bpB = pk2(bb), wpB = pk2(wxb);
            const ulonglong2* xv = reinterpret_cast<const ulonglong2*>(xs);
#pragma unroll
            for (int rv = 0; rv < 4; rv++) {
                ulonglong2 x2 = xv[rv];
                acc[2*rv+0] = bpA; fma2(acc[2*rv+0], wpA, x2.x);
                acc[2*rv+1] = bpA; fma2(acc[2*rv+1], wpA, x2.y);
                acc[8+2*rv+0] = bpB; fma2(acc[8+2*rv+0], wpB, x2.x);
                acc[8+2*rv+1] = bpB; fma2(acc[8+2*rv+1], wpB, x2.y);
            }
        } else {
#pragma unroll
            for (int k = 0; k < 16; k++) acc[k] = 0ULL;
        }
        // h1(-1) = 0, so no k-loop needed in the prologue
        ulonglong2* pwA = reinterpret_cast<ulonglong2*>(p1 + (kh1*JP + jp1)*PS);
        ulonglong2* pwB = reinterpret_cast<ulonglong2*>(p1 + (kh1*JP + jp1 + 104)*PS);
#pragma unroll
        for (int rv = 0; rv < 4; rv++) {
            ulonglong2 vA; vA.x = acc[2*rv+0];   vA.y = acc[2*rv+1];   pwA[rv] = vA;
            ulonglong2 vB; vB.x = acc[8+2*rv+0]; vB.y = acc[8+2*rv+1]; pwB[rv] = vB;
        }
    }
    __syncthreads();
    // update1(0)
    {
        int n = un;
        float gi = p1[(0*JP + 0*HP+n)*PS + ur] + p1[(1*JP + 0*HP+n)*PS + ur];
        float gf = p1[(0*JP + 1*HP+n)*PS + ur] + p1[(1*JP + 1*HP+n)*PS + ur];
        float gg = p1[(0*JP + 2*HP+n)*PS + ur] + p1[(1*JP + 2*HP+n)*PS + ur];
        float go = p1[(0*JP + 3*HP+n)*PS + ur] + p1[(1*JP + 3*HP+n)*PS + ur];
        c1 = siga(gf)*c1 + siga(gi)*tanha(gg);
        h1s[n*RR + ur] = siga(go)*tanha(c1);
    }
    if (has2) {
        int n = un2;
        float gi = p1[(0*JP + 0*HP+n)*PS + ur2] + p1[(1*JP + 0*HP+n)*PS + ur2];
        float gf = p1[(0*JP + 1*HP+n)*PS + ur2] + p1[(1*JP + 1*HP+n)*PS + ur2];
        float gg = p1[(0*JP + 2*HP+n)*PS + ur2] + p1[(1*JP + 2*HP+n)*PS + ur2];
        float go = p1[(0*JP + 3*HP+n)*PS + ur2] + p1[(1*JP + 3*HP+n)*PS + ur2];
        c1x = siga(gf)*c1x + siga(gi)*tanha(gg);
        h1s[n*RR + ur2] = siga(go)*tanha(c1x);
    }
    if (tid >= RR && tid < 2*RR) xs[tid - RR] = x1hold;   // xs = x(1)
    __syncthreads();

    // ================= main loop: 2 barriers per step =================
    for (int i = 0; i < TT; i++) {
        float xnext = 0.f;
        if (tid >= RR && tid < 2*RR && (i + 2) < TT)
            xnext = __ldg(&input[(row0 + tid - RR)*TT + i + 2]);

        // ---- slot M: phase2(i) | phase1(i+1) | out(i-1) ----
        if (isP2) {
            unsigned long long acc[16];
#pragma unroll
            for (int k = 0; k < 16; k++) acc[k] = 0ULL;
            const ulonglong2* hbase =
                reinterpret_cast<const ulonglong2*>((src ? h2s : h1s) + kh*26*RR);
#pragma unroll
            for (int kk = 0; kk < 26; kk++) {
                unsigned long long wA = pk2(wreg[kk]);
                unsigned long long wB = pk2(wreg[26 + kk]);
#pragma unroll
                for (int rv = 0; rv < 4; rv++) {
                    ulonglong2 h = hbase[kk*4 + rv];
                    fma2(acc[2*rv+0],   wA, h.x);
                    fma2(acc[2*rv+1],   wA, h.y);
                    fma2(acc[8+2*rv+0], wB, h.x);
                    fma2(acc[8+2*rv+1], wB, h.y);
                }
            }
            ulonglong2* pwA = reinterpret_cast<ulonglong2*>(p2 + (q*JP + jp)*PS);
            ulonglong2* pwB = reinterpret_cast<ulonglong2*>(p2 + (q*JP + jp + 104)*PS);
#pragma unroll
            for (int rv = 0; rv < 4; rv++) {
                ulonglong2 vA; vA.x = acc[2*rv+0];   vA.y = acc[2*rv+1];   pwA[rv] = vA;
                ulonglong2 vB; vB.x = acc[8+2*rv+0]; vB.y = acc[8+2*rv+1]; pwB[rv] = vB;
            }
        } else if (isP1) {
            // phase1(i+1): reads xs = x(i+1) (stale at i=TT-1: harmless garbage)
            unsigned long long acc[16];
            if (kh1 == 0) {
                unsigned long long bpA = pk2(ba), wpA = pk2(wxa);
                unsigned long long bpB = pk2(bb), wpB = pk2(wxb);
                const ulonglong2* xv = reinterpret_cast<const ulonglong2*>(xs);
#pragma unroll
                for (int rv = 0; rv < 4; rv++) {
                    ulonglong2 x2 = xv[rv];
                    acc[2*rv+0] = bpA; fma2(acc[2*rv+0], wpA, x2.x);
                    acc[2*rv+1] = bpA; fma2(acc[2*rv+1], wpA, x2.y);
                    acc[8+2*rv+0] = bpB; fma2(acc[8+2*rv+0], wpB, x2.x);
                    acc[8+2*rv+1] = bpB; fma2(acc[8+2*rv+1], wpB, x2.y);
                }
            } else {
#pragma unroll
                for (int k = 0; k < 16; k++) acc[k] = 0ULL;
            }
            const ulonglong2* hbase =
                reinterpret_cast<const ulonglong2*>(h1s + kh1*26*RR);
#pragma unroll
            for (int kk = 0; kk < 26; kk++) {
                unsigned long long wA = pk2(wreg[kk]);
                unsigned long long wB = pk2(wreg[26 + kk]);
#pragma unroll
                for (int rv = 0; rv < 4; rv++) {
                    ulonglong2 h = hbase[kk*4 + rv];
                    fma2(acc[2*rv+0],   wA, h.x);
                    fma2(acc[2*rv+1],   wA, h.y);
                    fma2(acc[8+2*rv+0], wB, h.x);
                    fma2(acc[8+2*rv+1], wB, h.y);
                }
            }
            ulonglong2* pwA = reinterpret_cast<ulonglong2*>(p1 + (kh1*JP + jp1)*PS);
            ulonglong2* pwB = reinterpret_cast<ulonglong2*>(p1 + (kh1*JP + jp1 + 104)*PS);
#pragma unroll
            for (int rv = 0; rv < 4; rv++) {
                ulonglong2 vA; vA.x = acc[2*rv+0];   vA.y = acc[2*rv+1];   pwA[rv] = vA;
                ulonglong2 vB; vB.x = acc[8+2*rv+0]; vB.y = acc[8+2*rv+1]; pwB[rv] = vB;
            }
        } else {
            // out(i-1): h2s holds h2(i-1) during slot M
            if (i > 0) {
                float s0 = 0.f, s1 = 0.f, s2 = 0.f, s3 = 0.f;
#pragma unroll
                for (int n = 0; n < HP; n += 4) {
                    s0 = fmaf(wls[n+0], h2s[(n+0)*RR + orow], s0);
                    s1 = fmaf(wls[n+1], h2s[(n+1)*RR + orow], s1);
                    s2 = fmaf(wls[n+2], h2s[(n+2)*RR + orow], s2);
                    s3 = fmaf(wls[n+3], h2s[(n+3)*RR + orow], s3);
                }
                out[(row0 + orow)*TT + (i - 1)] = (s0 + s1) + (s2 + s3) + blin;
            }
        }
        __syncthreads();

        // ---- slot U: update2(i) + update1(i+1) ----
        {
            int n = un;
            float gi = (p2[(0*JP + 0*HP+n)*PS + ur] + p2[(1*JP + 0*HP+n)*PS + ur])
                     + (p2[(2*JP + 0*HP+n)*PS + ur] + p2[(3*JP + 0*HP+n)*PS + ur]) + b2s[0*HP+n];
            float gf = (p2[(0*JP + 1*HP+n)*PS + ur] + p2[(1*JP + 1*HP+n)*PS + ur])
                     + (p2[(2*JP + 1*HP+n)*PS + ur] + p2[(3*JP + 1*HP+n)*PS + ur]) + b2s[1*HP+n];
            float gg = (p2[(0*JP + 2*HP+n)*PS + ur] + p2[(1*JP + 2*HP+n)*PS + ur])
                     + (p2[(2*JP + 2*HP+n)*PS + ur] + p2[(3*JP + 2*HP+n)*PS + ur]) + b2s[2*HP+n];
            float go = (p2[(0*JP + 3*HP+n)*PS + ur] + p2[(1*JP + 3*HP+n)*PS + ur])
                     + (p2[(2*JP + 3*HP+n)*PS + ur] + p2[(3*JP + 3*HP+n)*PS + ur]) + b2s[3*HP+n];
            c2 = siga(gf)*c2 + siga(gi)*tanha(gg);
            h2s[n*RR + ur] = siga(go)*tanha(c2);
        }
        if (has2) {
            int n = un2;
            float gi = (p2[(0*JP + 0*HP+n)*PS + ur2] + p2[(1*JP + 0*HP+n)*PS + ur2])
                     + (p2[(2*JP + 0*HP+n)*PS + ur2] + p2[(3*JP + 0*HP+n)*PS + ur2]) + b2s[0*HP+n];
            float gf = (p2[(0*JP + 1*HP+n)*PS + ur2] + p2[(1*JP + 1*HP+n)*PS + ur2])
                     + (p2[(2*JP + 1*HP+n)*PS + ur2] + p2[(3*JP + 1*HP+n)*PS + ur2]) + b2s[1*HP+n];
            float gg = (p2[(0*JP + 2*HP+n)*PS + ur2] + p2[(1*JP + 2*HP+n)*PS + ur2])
                     + (p2[(2*JP + 2*HP+n)*PS + ur2] + p2[(3*JP + 2*HP+n)*PS + ur2]) + b2s[2*HP+n];
            float go = (p2[(0*JP + 3*HP+n)*PS + ur2] + p2[(1*JP + 3*HP+n)*PS + ur2])
                     + (p2[(2*JP + 3*HP+n)*PS + ur2] + p2[(3*JP + 3*HP+n)*PS + ur2]) + b2s[3*HP+n];
            c2x = siga(gf)*c2x + siga(gi)*tanha(gg);
            h2s[n*RR + ur2] = siga(go)*tanha(c2x);
        }
        {
            int n = un;
            float gi = p1[(0*JP + 0*HP+n)*PS + ur] + p1[(1*JP + 0*HP+n)*PS + ur];
            float gf = p1[(0*JP + 1*HP+n)*PS + ur] + p1[(1*JP + 1*HP+n)*PS + ur];
            float gg = p1[(0*JP + 2*HP+n)*PS + ur] + p1[(1*JP + 2*HP+n)*PS + ur];
            float go = p1[(0*JP + 3*HP+n)*PS + ur] + p1[(1*JP + 3*HP+n)*PS + ur];
            c1 = siga(gf)*c1 + siga(gi)*tanha(gg);
            h1s[n*RR + ur] = siga(go)*tanha(c1);
        }
        if (has2) {
            int n = un2;
            float gi = p1[(0*JP + 0*HP+n)*PS + ur2] + p1[(1*JP + 0*HP+n)*PS + ur2];
            float gf = p1[(0*JP + 1*HP+n)*PS + ur2] + p1[(1*JP + 1*HP+n)*PS + ur2];
            float gg = p1[(0*JP + 2*HP+n)*PS + ur2] + p1[(1*JP + 2*HP+n)*PS + ur2];
            float go = p1[(0*JP + 3*HP+n)*PS + ur2] + p1[(1*JP + 3*HP+n)*PS + ur2];
            c1x = siga(gf)*c1x + siga(gi)*tanha(gg);
            h1s[n*RR + ur2] = siga(go)*tanha(c1x);
        }
        if (tid >= RR && tid < 2*RR && (i + 2) < TT) xs[tid - RR] = xnext;
        __syncthreads();
    }

    // ================= epilogue: out(TT-1) =================
    if (isOut) {
        float s0 = 0.f, s1 = 0.f, s2 = 0.f, s3 = 0.f;
#pragma unroll
        for (int n = 0; n < HP; n += 4) {
            s0 = fmaf(wls[n+0], h2s[(n+0)*RR + orow], s0);
            s1 = fmaf(wls[n+1], h2s[(n+1)*RR + orow], s1);
            s2 = fmaf(wls[n+2], h2s[(n+2)*RR + orow], s2);
            s3 = fmaf(wls[n+3], h2s[(n+3)*RR + orow], s3);
        }
        out[(row0 + orow)*TT + (TT - 1)] = (s0 + s1) + (s2 + s3) + blin;
    }
}

extern "C" void kernel_launch(void* const* d_in, const int* in_sizes, int n_in,
                              void* d_out, int out_size)
{
    const float* input = (const float*)d_in[0];
    const float* W_ih1 = (const float*)d_in[1];
    const float* W_hh1 = (const float*)d_in[2];
    const float* b_ih1 = (const float*)d_in[3];
    const float* b_hh1 = (const float*)d_in[4];
    const float* W_ih2 = (const float*)d_in[5];
    const float* W_hh2 = (const float*)d_in[6];
    const float* b_ih2 = (const float*)d_in[7];
    const float* b_hh2 = (const float*)d_in[8];
    const float* W_lin = (const float*)d_in[9];
    const float* b_lin = (const float*)d_in[10];
    float* out = (float*)d_out;

    const int smem_bytes = (416*PS + 832*PS + HP*RR*2 + RR + HP + JP) * (int)sizeof(float);
    cudaFuncSetAttribute(lstm_kernel, cudaFuncAttributeMaxDynamicSharedMemorySize, smem_bytes);

    prep_kernel<<<64, 256>>>(W_ih1, W_hh1, b_ih1, b_hh1,
                             W_ih2, W_hh2, b_ih2, b_hh2, W_lin, b_lin);
    lstm_kernel<<<BB/RR, NT, smem_bytes>>>(input, out);
}